// round 10
// baseline (speedup 1.0000x reference)
#include <cuda_runtime.h>

// DynamicMaskHead: per-instance 3-layer 1x1-conv MLP (10->8->8->1) over 27200 pixels.
// R10: f32x2 FMA, 4 px/thread, fused layer 0, per-bank layers 1-2 (lower reg peak,
// no hard cap), rel-y folded into bias, split layer-2 dot chains.

#define H_      136
#define W_      200
#define HW_     27200
#define CH_     8
#define INCH_   8
#define NINST_  128
#define NP_     169
#define STRIDE_ 8

#define BLK   256
#define NQ    (HW_ / 4)                 // 6800 float4 quads
#define GRIDX ((NQ + BLK - 1) / BLK)    // 27

typedef unsigned long long u64;

__device__ __forceinline__ u64 pack2(float lo, float hi) {
    u64 r; asm("mov.b64 %0, {%1, %2};" : "=l"(r) : "f"(lo), "f"(hi)); return r;
}
__device__ __forceinline__ u64 ffma2(u64 a, u64 b, u64 c) {
    u64 d; asm("fma.rn.f32x2 %0, %1, %2, %3;" : "=l"(d) : "l"(a), "l"(b), "l"(c)); return d;
}
__device__ __forceinline__ u64 fadd2(u64 a, u64 b) {
    u64 d; asm("add.rn.f32x2 %0, %1, %2;" : "=l"(d) : "l"(a), "l"(b)); return d;
}
__device__ __forceinline__ u64 relu2(u64 v) {
    float lo, hi;
    asm("mov.b64 {%0, %1}, %2;" : "=f"(lo), "=f"(hi) : "l"(v));
    return pack2(fmaxf(lo, 0.0f), fmaxf(hi, 0.0f));
}

// gmem params: w0 [0,80) (8x10) | w1 [80,144) (8x8) | w2 [144,152)
//              b0 [152,160) | b1 [160,168) | b2 [168]
struct __align__(16) SmemParams {
    u64 sw0t[80];   // sw0t[i*8+o] = w0[o][i]  (input-major, lane-duplicated)
    u64 sw1t[64];   // sw1t[i*8+o] = w1[o][i]
    u64 sw2[8];
    u64 sb0[8];
    u64 sb1[8];
    u64 sb2[2];
};

__global__ __launch_bounds__(BLK, 3)
void dmh_kernel(const float* __restrict__ feats,   // (2, 8, HW)
                const float* __restrict__ params,  // (128, 169)
                const float* __restrict__ locs,    // (128, 2)
                const float* __restrict__ soi,     // (5,)
                const int*   __restrict__ im_inds, // (128,)
                const int*   __restrict__ fpn,     // (128,)
                float*       __restrict__ out)     // (128, HW)
{
    __shared__ SmemParams S;
    __shared__ float smeta[3];
    __shared__ int   simg;

    const int inst = blockIdx.y;
    const int tid  = threadIdx.x;

    if (tid < NP_) {
        const float w = params[inst * NP_ + tid];
        const u64 d = pack2(w, w);
        if (tid < 80) {
            const int o = tid / 10, i = tid - o * 10;
            S.sw0t[i * 8 + o] = d;
        } else if (tid < 144) {
            const int k = tid - 80;
            S.sw1t[(k & 7) * 8 + (k >> 3)] = d;
        } else if (tid < 152) {
            S.sw2[tid - 144] = d;
        } else if (tid < 160) {
            S.sb0[tid - 152] = d;
        } else if (tid < 168) {
            S.sb1[tid - 160] = d;
        } else {
            S.sb2[0] = d;
        }
    }
    if (tid == 0) {
        smeta[0] = locs[2 * inst + 0];
        smeta[1] = locs[2 * inst + 1];
        smeta[2] = 1.0f / soi[fpn[inst]];
        simg     = im_inds[inst];
    }
    __syncthreads();

    const int q    = blockIdx.x * BLK + tid;
    const bool live = (q < NQ);
    const int qc   = live ? q : 0;
    const int p0   = qc * 4;                 // 4 consecutive pixels, one row

    // ---- front-batch the 8 feature-channel loads ----
    const float* __restrict__ fbase = feats + (size_t)simg * (INCH_ * HW_) + p0;
    ulonglong2 f[INCH_];
    #pragma unroll
    for (int c = 0; c < INCH_; c++)
        f[c] = *reinterpret_cast<const ulonglong2*>(fbase + (size_t)c * HW_);

    const int row  = qc / 50;
    const int col0 = (qc - row * 50) * 4;
    const float fy  = (float)(row * STRIDE_ + STRIDE_ / 2);
    const float fx0 = (float)(col0 * STRIDE_ + STRIDE_ / 2);
    const float locx = smeta[0];
    const float locy = smeta[1];
    const float inv  = smeta[2];

    // ---- layer 0: 10 -> 8 ; rel-y folded into bias (same for all 4 px) ----
    u64 h[2][CH_];
    {
        const float ry = (locy - fy) * inv;
        const u64 ry2 = pack2(ry, ry);
        const ulonglong2* b  = reinterpret_cast<const ulonglong2*>(S.sb0);
        const ulonglong2* wy = reinterpret_cast<const ulonglong2*>(&S.sw0t[8]);
        #pragma unroll
        for (int oq = 0; oq < 4; oq++) {
            const ulonglong2 bb = b[oq];
            const ulonglong2 ww = wy[oq];
            const u64 t0 = ffma2(ww.x, ry2, bb.x);
            const u64 t1 = ffma2(ww.y, ry2, bb.y);
            h[0][2*oq]   = t0;  h[1][2*oq]   = t0;
            h[0][2*oq+1] = t1;  h[1][2*oq+1] = t1;
        }
    }

    #define ACC2(WROW)                                                        \
        {                                                                     \
            const ulonglong2* wr = reinterpret_cast<const ulonglong2*>(WROW); \
            _Pragma("unroll")                                                 \
            for (int oq = 0; oq < 4; oq++) {                                  \
                const ulonglong2 w = wr[oq];                                  \
                h[0][2*oq]   = ffma2(w.x, x0, h[0][2*oq]);                    \
                h[1][2*oq]   = ffma2(w.x, x1, h[1][2*oq]);                    \
                h[0][2*oq+1] = ffma2(w.y, x0, h[0][2*oq+1]);                  \
                h[1][2*oq+1] = ffma2(w.y, x1, h[1][2*oq+1]);                  \
            }                                                                 \
        }

    {   // rel-x
        const u64 x0 = pack2((locx - fx0) * inv,           (locx - (fx0 +  8.0f)) * inv);
        const u64 x1 = pack2((locx - (fx0 + 16.0f)) * inv, (locx - (fx0 + 24.0f)) * inv);
        ACC2(&S.sw0t[0])
    }
    #pragma unroll
    for (int c = 0; c < INCH_; c++) {
        const u64 x0 = f[c].x;
        const u64 x1 = f[c].y;
        ACC2(&S.sw0t[(2 + c) * 8])
    }
    #undef ACC2

    #pragma unroll
    for (int o = 0; o < CH_; o++) {
        h[0][o] = relu2(h[0][o]);
        h[1][o] = relu2(h[1][o]);
    }

    // ---- layers 1+2 per bank (lower register peak) ----
    u64 res[2];
    #pragma unroll
    for (int bk = 0; bk < 2; bk++) {
        u64 a1[CH_];
        {
            const ulonglong2* b = reinterpret_cast<const ulonglong2*>(S.sb1);
            #pragma unroll
            for (int oq = 0; oq < 4; oq++) {
                const ulonglong2 bb = b[oq];
                a1[2*oq]   = bb.x;
                a1[2*oq+1] = bb.y;
            }
        }
        #pragma unroll
        for (int i = 0; i < CH_; i++) {
            const u64 x = h[bk][i];
            const ulonglong2* wr = reinterpret_cast<const ulonglong2*>(&S.sw1t[i * 8]);
            #pragma unroll
            for (int oq = 0; oq < 4; oq++) {
                const ulonglong2 w = wr[oq];
                a1[2*oq]   = ffma2(w.x, x, a1[2*oq]);
                a1[2*oq+1] = ffma2(w.y, x, a1[2*oq+1]);
            }
        }
        // layer 2 dot with two partial chains
        u64 rA = S.sb2[0];
        u64 rB = 0ULL;
        {
            const ulonglong2* wr = reinterpret_cast<const ulonglong2*>(S.sw2);
            #pragma unroll
            for (int iq = 0; iq < 4; iq++) {
                const ulonglong2 w = wr[iq];
                rA = ffma2(w.x, relu2(a1[2*iq]),   rA);
                rB = ffma2(w.y, relu2(a1[2*iq+1]), rB);
            }
        }
        res[bk] = fadd2(rA, rB);
    }

    if (live) {
        ulonglong2 o2;
        o2.x = res[0];
        o2.y = res[1];
        *reinterpret_cast<ulonglong2*>(out + (size_t)inst * HW_ + p0) = o2;
    }
}

extern "C" void kernel_launch(void* const* d_in, const int* in_sizes, int n_in,
                              void* d_out, int out_size)
{
    const float* feats   = (const float*)d_in[0];
    const float* params  = (const float*)d_in[1];
    const float* locs    = (const float*)d_in[2];
    const float* soi     = (const float*)d_in[3];
    const int*   im_inds = (const int*)  d_in[4];
    const int*   fpn     = (const int*)  d_in[5];
    float*       out     = (float*)      d_out;

    dim3 grid(GRIDX, NINST_);
    dmh_kernel<<<grid, BLK>>>(feats, params, locs, soi, im_inds, fpn, out);
}

// round 11
// speedup vs baseline: 3.2523x; 3.2523x over previous
#include <cuda_runtime.h>

// DynamicMaskHead: per-instance 3-layer 1x1-conv MLP (10->8->8->1) over 27200 pixels.
// R11 = R8 (best: 31.2us) + rel-y folded into bias + split layer-2 chains.
// Fused two-bank accumulators, front-batched feature LDGs, 4 px/thread.

#define H_      136
#define W_      200
#define HW_     27200
#define CH_     8
#define INCH_   8
#define NINST_  128
#define NP_     169
#define STRIDE_ 8

#define BLK   256
#define NQ    (HW_ / 4)                 // 6800 float4 quads
#define GRIDX ((NQ + BLK - 1) / BLK)    // 27

typedef unsigned long long u64;

__device__ __forceinline__ u64 pack2(float lo, float hi) {
    u64 r; asm("mov.b64 %0, {%1, %2};" : "=l"(r) : "f"(lo), "f"(hi)); return r;
}
__device__ __forceinline__ void unpack2(u64 v, float& lo, float& hi) {
    asm("mov.b64 {%0, %1}, %2;" : "=f"(lo), "=f"(hi) : "l"(v));
}
__device__ __forceinline__ u64 ffma2(u64 a, u64 b, u64 c) {
    u64 d; asm("fma.rn.f32x2 %0, %1, %2, %3;" : "=l"(d) : "l"(a), "l"(b), "l"(c)); return d;
}
__device__ __forceinline__ u64 fadd2(u64 a, u64 b) {
    u64 d; asm("add.rn.f32x2 %0, %1, %2;" : "=l"(d) : "l"(a), "l"(b)); return d;
}
__device__ __forceinline__ u64 relu2(u64 v) {
    float lo, hi; unpack2(v, lo, hi);
    return pack2(fmaxf(lo, 0.0f), fmaxf(hi, 0.0f));
}

// gmem params: w0 [0,80) (8x10) | w1 [80,144) (8x8) | w2 [144,152)
//              b0 [152,160) | b1 [160,168) | b2 [168]
struct __align__(16) SmemParams {
    u64 sw0t[80];   // sw0t[i*8+o] = w0[o][i]  (input-major, lane-duplicated)
    u64 sw1t[64];   // sw1t[i*8+o] = w1[o][i]
    u64 sw2[8];
    u64 sb0[8];
    u64 sb1[8];
    u64 sb2[2];
};

__global__ __launch_bounds__(BLK, 3)
void dmh_kernel(const float* __restrict__ feats,   // (2, 8, HW)
                const float* __restrict__ params,  // (128, 169)
                const float* __restrict__ locs,    // (128, 2)
                const float* __restrict__ soi,     // (5,)
                const int*   __restrict__ im_inds, // (128,)
                const int*   __restrict__ fpn,     // (128,)
                float*       __restrict__ out)     // (128, HW)
{
    __shared__ SmemParams S;
    __shared__ float smeta[3];
    __shared__ int   simg;

    const int inst = blockIdx.y;
    const int tid  = threadIdx.x;

    if (tid < NP_) {
        const float w = params[inst * NP_ + tid];
        const u64 d = pack2(w, w);
        if (tid < 80) {
            const int o = tid / 10, i = tid - o * 10;
            S.sw0t[i * 8 + o] = d;
        } else if (tid < 144) {
            const int k = tid - 80;
            S.sw1t[(k & 7) * 8 + (k >> 3)] = d;
        } else if (tid < 152) {
            S.sw2[tid - 144] = d;
        } else if (tid < 160) {
            S.sb0[tid - 152] = d;
        } else if (tid < 168) {
            S.sb1[tid - 160] = d;
        } else {
            S.sb2[0] = d;
        }
    }
    if (tid == 0) {
        smeta[0] = locs[2 * inst + 0];
        smeta[1] = locs[2 * inst + 1];
        smeta[2] = 1.0f / soi[fpn[inst]];
        simg     = im_inds[inst];
    }
    __syncthreads();

    const int q    = blockIdx.x * BLK + tid;
    const bool live = (q < NQ);
    const int qc   = live ? q : 0;
    const int p0   = qc * 4;                 // 4 consecutive pixels, one row

    // ---- front-batch all 8 feature-channel loads (independent, MLP=8) ----
    const float* __restrict__ fbase = feats + (size_t)simg * (INCH_ * HW_) + p0;
    ulonglong2 f[INCH_];
    #pragma unroll
    for (int c = 0; c < INCH_; c++)
        f[c] = *reinterpret_cast<const ulonglong2*>(fbase + (size_t)c * HW_);

    const int row  = qc / 50;
    const int col0 = (qc - row * 50) * 4;
    const float fy  = (float)(row * STRIDE_ + STRIDE_ / 2);
    const float fx0 = (float)(col0 * STRIDE_ + STRIDE_ / 2);
    const float locx = smeta[0];
    const float locy = smeta[1];
    const float inv  = smeta[2];

    // ---- layer 0: 10 -> 8 ; rel-y folded into bias (uniform over the quad) ----
    u64 h[2][CH_];
    {
        const float ry = (locy - fy) * inv;
        const u64 ry2 = pack2(ry, ry);
        const ulonglong2* b  = reinterpret_cast<const ulonglong2*>(S.sb0);
        const ulonglong2* wy = reinterpret_cast<const ulonglong2*>(&S.sw0t[8]);
        #pragma unroll
        for (int oq = 0; oq < 4; oq++) {
            const ulonglong2 bb = b[oq];
            const ulonglong2 ww = wy[oq];
            const u64 t0 = ffma2(ww.x, ry2, bb.x);
            const u64 t1 = ffma2(ww.y, ry2, bb.y);
            h[0][2*oq]   = t0;  h[1][2*oq]   = t0;
            h[0][2*oq+1] = t1;  h[1][2*oq+1] = t1;
        }
    }

    #define ACC2(WROW)                                                        \
        {                                                                     \
            const ulonglong2* wr = reinterpret_cast<const ulonglong2*>(WROW); \
            _Pragma("unroll")                                                 \
            for (int oq = 0; oq < 4; oq++) {                                  \
                const ulonglong2 w = wr[oq];                                  \
                h[0][2*oq]   = ffma2(w.x, x0, h[0][2*oq]);                    \
                h[1][2*oq]   = ffma2(w.x, x1, h[1][2*oq]);                    \
                h[0][2*oq+1] = ffma2(w.y, x0, h[0][2*oq+1]);                  \
                h[1][2*oq+1] = ffma2(w.y, x1, h[1][2*oq+1]);                  \
            }                                                                 \
        }

    {   // rel-x
        const u64 x0 = pack2((locx - fx0) * inv,           (locx - (fx0 +  8.0f)) * inv);
        const u64 x1 = pack2((locx - (fx0 + 16.0f)) * inv, (locx - (fx0 + 24.0f)) * inv);
        ACC2(&S.sw0t[0])
    }
    // feature channels
    #pragma unroll
    for (int c = 0; c < INCH_; c++) {
        const u64 x0 = f[c].x;
        const u64 x1 = f[c].y;
        ACC2(&S.sw0t[(2 + c) * 8])
    }
    #undef ACC2

    #pragma unroll
    for (int o = 0; o < CH_; o++) {
        h[0][o] = relu2(h[0][o]);
        h[1][o] = relu2(h[1][o]);
    }

    // ---- layer 1: 8 -> 8 (both banks fused, as in R8) ----
    u64 a1[2][CH_];
    {
        const ulonglong2* b = reinterpret_cast<const ulonglong2*>(S.sb1);
        #pragma unroll
        for (int oq = 0; oq < 4; oq++) {
            const ulonglong2 bb = b[oq];
            a1[0][2*oq]   = bb.x;  a1[1][2*oq]   = bb.x;
            a1[0][2*oq+1] = bb.y;  a1[1][2*oq+1] = bb.y;
        }
    }
    #pragma unroll
    for (int i = 0; i < CH_; i++) {
        const u64 x0 = h[0][i];
        const u64 x1 = h[1][i];
        const ulonglong2* wr = reinterpret_cast<const ulonglong2*>(&S.sw1t[i * 8]);
        #pragma unroll
        for (int oq = 0; oq < 4; oq++) {
            const ulonglong2 w = wr[oq];
            a1[0][2*oq]   = ffma2(w.x, x0, a1[0][2*oq]);
            a1[1][2*oq]   = ffma2(w.x, x1, a1[1][2*oq]);
            a1[0][2*oq+1] = ffma2(w.y, x0, a1[0][2*oq+1]);
            a1[1][2*oq+1] = ffma2(w.y, x1, a1[1][2*oq+1]);
        }
    }

    // ---- layer 2: 8 -> 1, two partial chains per bank (relu folded) ----
    u64 rA0 = S.sb2[0];
    u64 rA1 = rA0;
    u64 rB0 = 0ULL;
    u64 rB1 = 0ULL;
    {
        const ulonglong2* wr = reinterpret_cast<const ulonglong2*>(S.sw2);
        #pragma unroll
        for (int iq = 0; iq < 4; iq++) {
            const ulonglong2 w = wr[iq];
            rA0 = ffma2(w.x, relu2(a1[0][2*iq]),   rA0);
            rA1 = ffma2(w.x, relu2(a1[1][2*iq]),   rA1);
            rB0 = ffma2(w.y, relu2(a1[0][2*iq+1]), rB0);
            rB1 = ffma2(w.y, relu2(a1[1][2*iq+1]), rB1);
        }
    }

    if (live) {
        ulonglong2 o2;
        o2.x = fadd2(rA0, rB0);
        o2.y = fadd2(rA1, rB1);
        *reinterpret_cast<ulonglong2*>(out + (size_t)inst * HW_ + p0) = o2;
    }
}

extern "C" void kernel_launch(void* const* d_in, const int* in_sizes, int n_in,
                              void* d_out, int out_size)
{
    const float* feats   = (const float*)d_in[0];
    const float* params  = (const float*)d_in[1];
    const float* locs    = (const float*)d_in[2];
    const float* soi     = (const float*)d_in[3];
    const int*   im_inds = (const int*)  d_in[4];
    const int*   fpn     = (const int*)  d_in[5];
    float*       out     = (float*)      d_out;

    dim3 grid(GRIDX, NINST_);
    dmh_kernel<<<grid, BLK>>>(feats, params, locs, soi, im_inds, fpn, out);
}

// round 12
// speedup vs baseline: 3.2756x; 1.0072x over previous
#include <cuda_runtime.h>

// DynamicMaskHead: per-instance 3-layer 1x1-conv MLP (10->8->8->1) over 27200 pixels.
// R12 = R11 + prologue overlap: feature LDGs + meta broadcast-LDGs issued BEFORE
// __syncthreads so param staging latency is hidden; no shared meta round-trip.

#define H_      136
#define W_      200
#define HW_     27200
#define CH_     8
#define INCH_   8
#define NINST_  128
#define NP_     169
#define STRIDE_ 8

#define BLK   256
#define NQ    (HW_ / 4)                 // 6800 float4 quads
#define GRIDX ((NQ + BLK - 1) / BLK)    // 27

typedef unsigned long long u64;

__device__ __forceinline__ u64 pack2(float lo, float hi) {
    u64 r; asm("mov.b64 %0, {%1, %2};" : "=l"(r) : "f"(lo), "f"(hi)); return r;
}
__device__ __forceinline__ void unpack2(u64 v, float& lo, float& hi) {
    asm("mov.b64 {%0, %1}, %2;" : "=f"(lo), "=f"(hi) : "l"(v));
}
__device__ __forceinline__ u64 ffma2(u64 a, u64 b, u64 c) {
    u64 d; asm("fma.rn.f32x2 %0, %1, %2, %3;" : "=l"(d) : "l"(a), "l"(b), "l"(c)); return d;
}
__device__ __forceinline__ u64 fadd2(u64 a, u64 b) {
    u64 d; asm("add.rn.f32x2 %0, %1, %2;" : "=l"(d) : "l"(a), "l"(b)); return d;
}
__device__ __forceinline__ u64 relu2(u64 v) {
    float lo, hi; unpack2(v, lo, hi);
    return pack2(fmaxf(lo, 0.0f), fmaxf(hi, 0.0f));
}

// gmem params: w0 [0,80) (8x10) | w1 [80,144) (8x8) | w2 [144,152)
//              b0 [152,160) | b1 [160,168) | b2 [168]
struct __align__(16) SmemParams {
    u64 sw0t[80];   // sw0t[i*8+o] = w0[o][i]  (input-major, lane-duplicated)
    u64 sw1t[64];   // sw1t[i*8+o] = w1[o][i]
    u64 sw2[8];
    u64 sb0[8];
    u64 sb1[8];
    u64 sb2[2];
};

__global__ __launch_bounds__(BLK, 3)
void dmh_kernel(const float* __restrict__ feats,   // (2, 8, HW)
                const float* __restrict__ params,  // (128, 169)
                const float* __restrict__ locs,    // (128, 2)
                const float* __restrict__ soi,     // (5,)
                const int*   __restrict__ im_inds, // (128,)
                const int*   __restrict__ fpn,     // (128,)
                float*       __restrict__ out)     // (128, HW)
{
    __shared__ SmemParams S;

    const int inst = blockIdx.y;
    const int tid  = threadIdx.x;

    // ---- param staging LDG (latency overlapped with everything below) ----
    float wstage = 0.0f;
    if (tid < NP_) wstage = params[inst * NP_ + tid];

    // ---- meta via broadcast LDGs (uniform across block, L2-hit) ----
    const int   simg = im_inds[inst];
    const float locx = locs[2 * inst + 0];
    const float locy = locs[2 * inst + 1];
    const float inv  = 1.0f / soi[fpn[inst]];

    const int q    = blockIdx.x * BLK + tid;
    const bool live = (q < NQ);
    const int qc   = live ? q : 0;
    const int p0   = qc * 4;                 // 4 consecutive pixels, one row

    // ---- front-batch all 8 feature-channel loads (independent of smem) ----
    const float* __restrict__ fbase = feats + (size_t)simg * (INCH_ * HW_) + p0;
    ulonglong2 f[INCH_];
    #pragma unroll
    for (int c = 0; c < INCH_; c++)
        f[c] = *reinterpret_cast<const ulonglong2*>(fbase + (size_t)c * HW_);

    // ---- rel coords (pure ALU, overlaps staging + feature LDGs) ----
    const int row  = qc / 50;
    const int col0 = (qc - row * 50) * 4;
    const float fy  = (float)(row * STRIDE_ + STRIDE_ / 2);
    const float fx0 = (float)(col0 * STRIDE_ + STRIDE_ / 2);
    const float ry  = (locy - fy) * inv;
    const u64 ry2 = pack2(ry, ry);
    const u64 rx0 = pack2((locx - fx0) * inv,           (locx - (fx0 +  8.0f)) * inv);
    const u64 rx1 = pack2((locx - (fx0 + 16.0f)) * inv, (locx - (fx0 + 24.0f)) * inv);

    // ---- write staged params to shared, then sync ----
    if (tid < NP_) {
        const u64 d = pack2(wstage, wstage);
        if (tid < 80) {
            const int o = tid / 10, i = tid - o * 10;
            S.sw0t[i * 8 + o] = d;
        } else if (tid < 144) {
            const int k = tid - 80;
            S.sw1t[(k & 7) * 8 + (k >> 3)] = d;
        } else if (tid < 152) {
            S.sw2[tid - 144] = d;
        } else if (tid < 160) {
            S.sb0[tid - 152] = d;
        } else if (tid < 168) {
            S.sb1[tid - 160] = d;
        } else {
            S.sb2[0] = d;
        }
    }
    __syncthreads();

    // ---- layer 0: 10 -> 8 ; rel-y folded into bias (uniform over the quad) ----
    u64 h[2][CH_];
    {
        const ulonglong2* b  = reinterpret_cast<const ulonglong2*>(S.sb0);
        const ulonglong2* wy = reinterpret_cast<const ulonglong2*>(&S.sw0t[8]);
        #pragma unroll
        for (int oq = 0; oq < 4; oq++) {
            const ulonglong2 bb = b[oq];
            const ulonglong2 ww = wy[oq];
            const u64 t0 = ffma2(ww.x, ry2, bb.x);
            const u64 t1 = ffma2(ww.y, ry2, bb.y);
            h[0][2*oq]   = t0;  h[1][2*oq]   = t0;
            h[0][2*oq+1] = t1;  h[1][2*oq+1] = t1;
        }
    }

    #define ACC2(WROW)                                                        \
        {                                                                     \
            const ulonglong2* wr = reinterpret_cast<const ulonglong2*>(WROW); \
            _Pragma("unroll")                                                 \
            for (int oq = 0; oq < 4; oq++) {                                  \
                const ulonglong2 w = wr[oq];                                  \
                h[0][2*oq]   = ffma2(w.x, x0, h[0][2*oq]);                    \
                h[1][2*oq]   = ffma2(w.x, x1, h[1][2*oq]);                    \
                h[0][2*oq+1] = ffma2(w.y, x0, h[0][2*oq+1]);                  \
                h[1][2*oq+1] = ffma2(w.y, x1, h[1][2*oq+1]);                  \
            }                                                                 \
        }

    {   // rel-x
        const u64 x0 = rx0;
        const u64 x1 = rx1;
        ACC2(&S.sw0t[0])
    }
    // feature channels
    #pragma unroll
    for (int c = 0; c < INCH_; c++) {
        const u64 x0 = f[c].x;
        const u64 x1 = f[c].y;
        ACC2(&S.sw0t[(2 + c) * 8])
    }
    #undef ACC2

    #pragma unroll
    for (int o = 0; o < CH_; o++) {
        h[0][o] = relu2(h[0][o]);
        h[1][o] = relu2(h[1][o]);
    }

    // ---- layer 1: 8 -> 8 (both banks fused) ----
    u64 a1[2][CH_];
    {
        const ulonglong2* b = reinterpret_cast<const ulonglong2*>(S.sb1);
        #pragma unroll
        for (int oq = 0; oq < 4; oq++) {
            const ulonglong2 bb = b[oq];
            a1[0][2*oq]   = bb.x;  a1[1][2*oq]   = bb.x;
            a1[0][2*oq+1] = bb.y;  a1[1][2*oq+1] = bb.y;
        }
    }
    #pragma unroll
    for (int i = 0; i < CH_; i++) {
        const u64 x0 = h[0][i];
        const u64 x1 = h[1][i];
        const ulonglong2* wr = reinterpret_cast<const ulonglong2*>(&S.sw1t[i * 8]);
        #pragma unroll
        for (int oq = 0; oq < 4; oq++) {
            const ulonglong2 w = wr[oq];
            a1[0][2*oq]   = ffma2(w.x, x0, a1[0][2*oq]);
            a1[1][2*oq]   = ffma2(w.x, x1, a1[1][2*oq]);
            a1[0][2*oq+1] = ffma2(w.y, x0, a1[0][2*oq+1]);
            a1[1][2*oq+1] = ffma2(w.y, x1, a1[1][2*oq+1]);
        }
    }

    // ---- layer 2: 8 -> 1, two partial chains per bank (relu folded) ----
    u64 rA0 = S.sb2[0];
    u64 rA1 = rA0;
    u64 rB0 = 0ULL;
    u64 rB1 = 0ULL;
    {
        const ulonglong2* wr = reinterpret_cast<const ulonglong2*>(S.sw2);
        #pragma unroll
        for (int iq = 0; iq < 4; iq++) {
            const ulonglong2 w = wr[iq];
            rA0 = ffma2(w.x, relu2(a1[0][2*iq]),   rA0);
            rA1 = ffma2(w.x, relu2(a1[1][2*iq]),   rA1);
            rB0 = ffma2(w.y, relu2(a1[0][2*iq+1]), rB0);
            rB1 = ffma2(w.y, relu2(a1[1][2*iq+1]), rB1);
        }
    }

    if (live) {
        ulonglong2 o2;
        o2.x = fadd2(rA0, rB0);
        o2.y = fadd2(rA1, rB1);
        *reinterpret_cast<ulonglong2*>(out + (size_t)inst * HW_ + p0) = o2;
    }
}

extern "C" void kernel_launch(void* const* d_in, const int* in_sizes, int n_in,
                              void* d_out, int out_size)
{
    const float* feats   = (const float*)d_in[0];
    const float* params  = (const float*)d_in[1];
    const float* locs    = (const float*)d_in[2];
    const float* soi     = (const float*)d_in[3];
    const int*   im_inds = (const int*)  d_in[4];
    const int*   fpn     = (const int*)  d_in[5];
    float*       out     = (float*)      d_out;

    dim3 grid(GRIDX, NINST_);
    dmh_kernel<<<grid, BLK>>>(feats, params, locs, soi, im_inds, fpn, out);
}